// round 11
// baseline (speedup 1.0000x reference)
#include <cuda_runtime.h>
#include <stdint.h>

// ---------------------------------------------------------------------------
// Persistent fp32 RNN, k-pair packed f32x2, one-barrier-per-step pipeline,
// two-level (count -> flag) inter-CTA release.
//
// out[t] = tanh(x[t] @ Wi^T + h @ Wh^T),  h = out[t]
//
// 8 batch-groups x 16 H-slice CTAs = 128 CTAs, 512 threads (16 warps).
// Warp w owns h k-pairs [16w,16w+16) and x k-pairs [KP_H+8w,+8), both staged
// warp-privately. Releases: each warp acq_rel-adds a per-CTA global count;
// the 16th arriver releases the per-CTA flag ONCE per step (cheap spin).
// Ps double-buffered by parity -> single __syncthreads per step.
// ---------------------------------------------------------------------------

namespace {
constexpr int kT = 1024, kB = 128, kI = 256, kH = 512;
constexpr int NG = 8, BG = 16, NC = 16, JC = 32;
constexpr int NTHR = 512, NWARP = 16;
constexpr int KP_H = kH / 2;          // 256
constexpr int KP_X = kI / 2;          // 128
constexpr int KPT  = KP_H + KP_X;     // 384
constexpr int XW = KP_X / NWARP;      // 8 x k-pairs per warp
constexpr int HW = KP_H / NWARP;      // 16 h k-pairs per warp

constexpr int WS_STRIDE = 34;         // u64 per weight row
constexpr int HD_STRIDE = 18;         // u64 per Hd row (16 cols + pad)
constexpr int PS_STRIDE = 34;         // floats per Ps row
constexpr int PS_FLOATS = NWARP * BG * PS_STRIDE;   // per parity buffer

constexpr int OFF_WS = 0;
constexpr int OFF_HD = KPT * WS_STRIDE;             // u64 units
constexpr int OFF_PS = OFF_HD + KPT * HD_STRIDE;
constexpr int OFF_AUX = OFF_PS + PS_FLOATS;         // after 2 parity buffers
constexpr int SMEM_U64 = OFF_AUX + 1;
constexpr size_t SMEM_BYTES = size_t(SMEM_U64) * 8; // ~224 KB
}

__device__ unsigned g_rnn_flag[NG * NC];   // zero-init; monotonic forever
__device__ unsigned g_rnn_cnt[NG * NC];    // zero-init; monotonic forever

__device__ __forceinline__ void fma2(unsigned long long& acc,
                                     unsigned long long a,
                                     unsigned long long b) {
    asm("fma.rn.f32x2 %0, %1, %2, %0;" : "+l"(acc) : "l"(a), "l"(b));
}

#define STEP16(wp, hp)                                                       \
    do {                                                                     \
        const ulonglong2 w0 = *reinterpret_cast<const ulonglong2*>(wp);      \
        const ulonglong2 w1 = *reinterpret_cast<const ulonglong2*>((wp)+16); \
        const ulonglong2 h0 = *reinterpret_cast<const ulonglong2*>(hp);      \
        const ulonglong2 h1 = *reinterpret_cast<const ulonglong2*>((hp)+2);  \
        fma2(acc[0],  w0.x, h0.x); fma2(acc[4],  w0.y, h0.x);                \
        fma2(acc[8],  w1.x, h0.x); fma2(acc[12], w1.y, h0.x);                \
        fma2(acc[1],  w0.x, h0.y); fma2(acc[5],  w0.y, h0.y);                \
        fma2(acc[9],  w1.x, h0.y); fma2(acc[13], w1.y, h0.y);                \
        fma2(acc[2],  w0.x, h1.x); fma2(acc[6],  w0.y, h1.x);                \
        fma2(acc[10], w1.x, h1.x); fma2(acc[14], w1.y, h1.x);                \
        fma2(acc[3],  w0.x, h1.y); fma2(acc[7],  w0.y, h1.y);                \
        fma2(acc[11], w1.x, h1.y); fma2(acc[15], w1.y, h1.y);                \
    } while (0)

__global__ void __launch_bounds__(NTHR, 1)
rnn_2lvl_kernel(const float* __restrict__ x,
                const float* __restrict__ Wi,
                const float* __restrict__ Wh,
                float* __restrict__ out,
                int write_tail)
{
    extern __shared__ unsigned long long smu[];
    unsigned long long* Ws = smu + OFF_WS;
    unsigned long long* Hd = smu + OFF_HD;
    float*              Ps = reinterpret_cast<float*>(smu + OFF_PS);
    unsigned*           Aux = reinterpret_cast<unsigned*>(smu + OFF_AUX);

    const int tid = threadIdx.x;
    const int g   = blockIdx.x >> 4;
    const int c   = blockIdx.x & 15;
    const int bg0 = g * BG;
    const int jg0 = c * JC;

    // ---- prologue ----------------------------------------------------------
    if (tid == 0) Aux[0] = g_rnn_flag[blockIdx.x];   // all flags equal at launch

    {   // weights, column-permuted: dst(j) = (j>>2)*2 + ((j>>1)&1)*16 + (j&1)
        const int jl  = tid >> 4;
        const int kpb = tid & 15;
        const int dst = (jl >> 2) * 2 + ((jl >> 1) & 1) * 16 + (jl & 1);
        const float2* whp = reinterpret_cast<const float2*>(
            Wh + (size_t)(jg0 + jl) * kH);
        #pragma unroll
        for (int i = 0; i < KP_H / 16; ++i) {
            int kp = kpb + 16 * i;
            float2 v = __ldg(whp + kp);
            Ws[kp * WS_STRIDE + dst] = *reinterpret_cast<unsigned long long*>(&v);
        }
        const float2* wip = reinterpret_cast<const float2*>(
            Wi + (size_t)(jg0 + jl) * kI);
        #pragma unroll
        for (int i = 0; i < KP_X / 16; ++i) {
            int kp = kpb + 16 * i;
            float2 v = __ldg(wip + kp);
            Ws[(KP_H + kp) * WS_STRIDE + dst] =
                *reinterpret_cast<unsigned long long*>(&v);
        }
    }
    for (int e = tid; e < KP_H * HD_STRIDE; e += NTHR) Hd[e] = 0ull;
    {   // x[0]: col = b ^ 4*((row>>3)&3)
        const int b = tid >> 5, l = tid & 31;
        const int col = b ^ (4 * ((l >> 3) & 3));
        const float2* xp = reinterpret_cast<const float2*>(
            x + (size_t)(bg0 + b) * kI);
        #pragma unroll
        for (int i = 0; i < 4; ++i) {
            float2 v = __ldcg(xp + l + 32 * i);
            Hd[(KP_H + l + 32 * i) * HD_STRIDE + col] =
                *reinterpret_cast<unsigned long long*>(&v);
        }
    }
    __syncthreads();
    const unsigned base = Aux[0];

    // ---- per-thread geometry ------------------------------------------------
    const int w    = tid >> 5;
    const int lane = tid & 31;
    const int jq   = lane & 7;
    const int bp   = lane >> 3;
    const int rb   = w, rl = lane;

    volatile unsigned* flagp = g_rnn_flag + (g * NC + w);
    unsigned* myflag = g_rnn_flag + blockIdx.x;
    unsigned* mycnt  = g_rnn_cnt  + blockIdx.x;

    // h readback geometry (warp w <- producer CTA (g,w), j in [32w,32w+32))
    const int p    = lane & 15;
    const int bh   = (lane >> 4) * 8;
    const int pge8 = (p >> 3) & 1;
    const int hswz = 4 * ((2 * w + pge8) & 3);

    // warp-private x staging geometry: rows KP_H+8w+r, r = lane&7
    const int xr_row = lane & 7;
    const int xq     = lane >> 3;
    const int xswz   = 4 * (w & 3);

    const unsigned long long* wx  = Ws + (size_t)(KP_H + XW * w) * WS_STRIDE + jq * 2;
    const unsigned long long* hx  = Hd + (size_t)(KP_H + XW * w) * HD_STRIDE
                                       + 4 * (bp ^ (w & 3));
    const unsigned long long* wh0 = Ws + (size_t)(HW * w) * WS_STRIDE + jq * 2;
    const unsigned long long* hh0 = Hd + (size_t)(HW * w) * HD_STRIDE
                                       + 4 * (bp ^ ((2 * w) & 3));
    const unsigned long long* wh1 = Ws + (size_t)(HW * w + 8) * WS_STRIDE + jq * 2;
    const unsigned long long* hh1 = Hd + (size_t)(HW * w + 8) * HD_STRIDE
                                       + 4 * (bp ^ ((2 * w + 1) & 3));

    unsigned long long acc[16];

    // ---- x-part for t=0 ------------------------------------------------------
    {
        #pragma unroll
        for (int i = 0; i < 16; ++i) acc[i] = 0ull;
        const unsigned long long* wp = wx;
        const unsigned long long* hp = hx;
        #pragma unroll
        for (int i = 0; i < XW; ++i) { STEP16(wp, hp); wp += WS_STRIDE; hp += HD_STRIDE; }
    }

    for (int t = 0; t < kT; ++t) {
        float* Psb = Ps + (t & 1) * PS_FLOATS;

        // ---- h-part ----------------------------------------------------------
        {
            const unsigned long long* wp = wh0;
            const unsigned long long* hp = hh0;
            #pragma unroll
            for (int i = 0; i < 8; ++i) { STEP16(wp, hp); wp += WS_STRIDE; hp += HD_STRIDE; }
            wp = wh1; hp = hh1;
            #pragma unroll
            for (int i = 0; i < 8; ++i) { STEP16(wp, hp); wp += WS_STRIDE; hp += HD_STRIDE; }
        }

        // ---- scatter partials (conflict-free) --------------------------------
        #pragma unroll
        for (int bb = 0; bb < 4; ++bb) {
            const int row = (w * BG + 4 * bp + bb) * PS_STRIDE;
            #pragma unroll
            for (int jj = 0; jj < 4; ++jj) {
                float2 f = *reinterpret_cast<float2*>(&acc[jj * 4 + bb]);
                Psb[row + jj * 8 + jq] = f.x + f.y;
            }
        }

        // ---- issue x[t+1] loads (warp-private rows) ---------------------------
        float2 xv[4];
        if (t + 1 < kT) {
            #pragma unroll
            for (int i = 0; i < 4; ++i) {
                const int b = 4 * xq + i;
                xv[i] = __ldcg(reinterpret_cast<const float2*>(
                    x + (size_t)(t + 1) * kB * kI + (size_t)(bg0 + b) * kI)
                    + (XW * w + xr_row));
            }
        }
        __syncthreads();                                   // S1: Ps ready

        // ---- reduce, tanh, store out[t] ----------------------------------------
        {
            const int cf = (rl & 3) * 8 + (rl >> 2);
            float pv[16];
            #pragma unroll
            for (int ws = 0; ws < NWARP; ++ws)
                pv[ws] = Psb[(ws * BG + rb) * PS_STRIDE + cf];
            #pragma unroll
            for (int s = 8; s >= 1; s >>= 1)
                #pragma unroll
                for (int i = 0; i < s; ++i) pv[i] += pv[i + s];
            float r = tanhf(pv[0]);
            size_t o = (size_t)t * kB * kH + (size_t)(bg0 + rb) * kH + jg0 + rl;
            out[o] = r;
            if (t == kT - 1 && write_tail)
                out[(size_t)kT * kB * kH + (size_t)(bg0 + rb) * kH + jg0 + rl] = r;
        }
        if (t + 1 == kT) break;

        // ---- per-warp arrival on per-CTA count (release; latency hidden) -------
        __syncwarp();
        unsigned old = 0;
        if (lane == 0) {
            asm volatile("atom.acq_rel.gpu.global.add.u32 %0, [%1], %2;"
                         : "=r"(old) : "l"(mycnt), "r"(1u) : "memory");
        }

        // ---- stage x[t+1] into OWN rows (independent of atom) -------------------
        #pragma unroll
        for (int i = 0; i < 4; ++i) {
            const int b = 4 * xq + i;
            Hd[(size_t)(KP_H + XW * w + xr_row) * HD_STRIDE + (b ^ xswz)] =
                *reinterpret_cast<unsigned long long*>(&xv[i]);
        }

        // ---- last arriver releases the flag ONCE --------------------------------
        if (lane == 0 && (old & 15u) == 15u) {
            asm volatile("red.release.gpu.global.add.u32 [%0], %1;"
                         :: "l"(myflag), "r"(1u) : "memory");
        }
        __syncwarp();

        // ---- x-part(t+1): overlaps producer release->visibility -----------------
        {
            #pragma unroll
            for (int i = 0; i < 16; ++i) acc[i] = 0ull;
            const unsigned long long* wp = wx;
            const unsigned long long* hp = hx;
            #pragma unroll
            for (int i = 0; i < XW; ++i) { STEP16(wp, hp); wp += WS_STRIDE; hp += HD_STRIDE; }
        }

        // ---- wait producer flag (single increment), read h slice, stage ---------
        {
            const unsigned target = base + (unsigned)(t + 1);
            unsigned cur;
            do {
                asm volatile("ld.acquire.gpu.global.u32 %0, [%1];"
                             : "=r"(cur) : "l"((const unsigned*)flagp) : "memory");
            } while ((int)(cur - target) < 0);

            const float* hb = out + (size_t)t * kB * kH + (size_t)bg0 * kH
                                  + 32 * w + 2 * p;
            float2 hv[8];
            #pragma unroll
            for (int i = 0; i < 8; ++i) {
                const int brd = ((((2 * i) & 6) | (i >> 2)) ^ pge8);
                hv[i] = __ldcg(reinterpret_cast<const float2*>(
                    hb + (size_t)(bh + brd) * kH));
            }
            #pragma unroll
            for (int i = 0; i < 8; ++i) {
                const int brd = ((((2 * i) & 6) | (i >> 2)) ^ pge8);
                Hd[(16 * w + p) * HD_STRIDE + ((bh + brd) ^ hswz)] =
                    *reinterpret_cast<unsigned long long*>(&hv[i]);
            }
            __syncwarp();
        }
    }
}

extern "C" void kernel_launch(void* const* d_in, const int* in_sizes, int n_in,
                              void* d_out, int out_size) {
    const float* x  = (const float*)d_in[0];   // [T,B,I]
    const float* Wi = (const float*)d_in[1];   // [H,I]
    const float* Wh = (const float*)d_in[2];   // [H,H]
    float* out = (float*)d_out;

    const long long main_elems = (long long)kT * kB * kH;
    int write_tail = ((long long)out_size >= main_elems + (long long)kB * kH) ? 1 : 0;

    cudaFuncSetAttribute(rnn_2lvl_kernel,
                         cudaFuncAttributeMaxDynamicSharedMemorySize,
                         (int)SMEM_BYTES);
    rnn_2lvl_kernel<<<NG * NC, NTHR, SMEM_BYTES>>>(x, Wi, Wh, out, write_tail);
}

// round 12
// speedup vs baseline: 1.2027x; 1.2027x over previous
#include <cuda_runtime.h>
#include <stdint.h>

// ---------------------------------------------------------------------------
// Persistent fp32 RNN, k-pair packed f32x2 (R6 protocol + de-blocked release).
//
// out[t] = tanh(x[t] @ Wi^T + h @ Wh^T),  h = out[t]
//
// 8 batch-groups x 16 H-slice CTAs = 128 CTAs, 512 threads (16 warps).
// R6 skeleton: per-CTA monotonic flag released ONCE per step; consumer warp w
// spins only on producer CTA (g,w). New: S2 replaced by bar.arrive(1)/bar.sync
// (only warp 0 blocks, then tid0 fence.acq_rel.gpu + red.release); warp-
// private x staging; Ps parity double-buffer; early relaxed flag poll.
// ---------------------------------------------------------------------------

namespace {
constexpr int kT = 1024, kB = 128, kI = 256, kH = 512;
constexpr int NG = 8, BG = 16, NC = 16, JC = 32;
constexpr int NTHR = 512, NWARP = 16;
constexpr int KP_H = kH / 2;          // 256
constexpr int KP_X = kI / 2;          // 128
constexpr int KPT  = KP_H + KP_X;     // 384
constexpr int XW = KP_X / NWARP;      // 8 x k-pairs per warp
constexpr int HW = KP_H / NWARP;      // 16 h k-pairs per warp

constexpr int WS_STRIDE = 34;         // u64 per weight row
constexpr int HD_STRIDE = 18;         // u64 per Hd row (16 cols + pad)
constexpr int PS_STRIDE = 34;         // floats per Ps row
constexpr int PS_FLOATS = NWARP * BG * PS_STRIDE;   // 8704 per parity buffer

constexpr int OFF_WS = 0;
constexpr int OFF_HD = KPT * WS_STRIDE;             // u64 units
constexpr int OFF_PS = OFF_HD + KPT * HD_STRIDE;
constexpr int OFF_AUX = OFF_PS + PS_FLOATS;         // after 2 parity buffers
constexpr int SMEM_U64 = OFF_AUX + 1;
constexpr size_t SMEM_BYTES = size_t(SMEM_U64) * 8; // ~224 KB
}

__device__ unsigned g_rnn_flag[NG * NC];   // zero-init; monotonic forever

__device__ __forceinline__ void fma2(unsigned long long& acc,
                                     unsigned long long a,
                                     unsigned long long b) {
    asm("fma.rn.f32x2 %0, %1, %2, %0;" : "+l"(acc) : "l"(a), "l"(b));
}

#define STEP16(wp, hp)                                                       \
    do {                                                                     \
        const ulonglong2 w0 = *reinterpret_cast<const ulonglong2*>(wp);      \
        const ulonglong2 w1 = *reinterpret_cast<const ulonglong2*>((wp)+16); \
        const ulonglong2 h0 = *reinterpret_cast<const ulonglong2*>(hp);      \
        const ulonglong2 h1 = *reinterpret_cast<const ulonglong2*>((hp)+2);  \
        fma2(acc[0],  w0.x, h0.x); fma2(acc[4],  w0.y, h0.x);                \
        fma2(acc[8],  w1.x, h0.x); fma2(acc[12], w1.y, h0.x);                \
        fma2(acc[1],  w0.x, h0.y); fma2(acc[5],  w0.y, h0.y);                \
        fma2(acc[9],  w1.x, h0.y); fma2(acc[13], w1.y, h0.y);                \
        fma2(acc[2],  w0.x, h1.x); fma2(acc[6],  w0.y, h1.x);                \
        fma2(acc[10], w1.x, h1.x); fma2(acc[14], w1.y, h1.x);                \
        fma2(acc[3],  w0.x, h1.y); fma2(acc[7],  w0.y, h1.y);                \
        fma2(acc[11], w1.x, h1.y); fma2(acc[15], w1.y, h1.y);                \
    } while (0)

__global__ void __launch_bounds__(NTHR, 1)
rnn_deblk_kernel(const float* __restrict__ x,
                 const float* __restrict__ Wi,
                 const float* __restrict__ Wh,
                 float* __restrict__ out,
                 int write_tail)
{
    extern __shared__ unsigned long long smu[];
    unsigned long long* Ws = smu + OFF_WS;
    unsigned long long* Hd = smu + OFF_HD;
    float*              Ps = reinterpret_cast<float*>(smu + OFF_PS);
    unsigned*           Aux = reinterpret_cast<unsigned*>(smu + OFF_AUX);

    const int tid = threadIdx.x;
    const int g   = blockIdx.x >> 4;
    const int c   = blockIdx.x & 15;
    const int bg0 = g * BG;
    const int jg0 = c * JC;

    // ---- prologue ----------------------------------------------------------
    if (tid == 0) Aux[0] = g_rnn_flag[blockIdx.x];   // all flags equal at launch

    {   // weights, column-permuted: dst(j) = (j>>2)*2 + ((j>>1)&1)*16 + (j&1)
        const int jl  = tid >> 4;
        const int kpb = tid & 15;
        const int dst = (jl >> 2) * 2 + ((jl >> 1) & 1) * 16 + (jl & 1);
        const float2* whp = reinterpret_cast<const float2*>(
            Wh + (size_t)(jg0 + jl) * kH);
        #pragma unroll
        for (int i = 0; i < KP_H / 16; ++i) {
            int kp = kpb + 16 * i;
            float2 v = __ldg(whp + kp);
            Ws[kp * WS_STRIDE + dst] = *reinterpret_cast<unsigned long long*>(&v);
        }
        const float2* wip = reinterpret_cast<const float2*>(
            Wi + (size_t)(jg0 + jl) * kI);
        #pragma unroll
        for (int i = 0; i < KP_X / 16; ++i) {
            int kp = kpb + 16 * i;
            float2 v = __ldg(wip + kp);
            Ws[(KP_H + kp) * WS_STRIDE + dst] =
                *reinterpret_cast<unsigned long long*>(&v);
        }
    }
    for (int e = tid; e < KP_H * HD_STRIDE; e += NTHR) Hd[e] = 0ull;
    {   // x[0]: col = b ^ 4*((row>>3)&3)
        const int b = tid >> 5, l = tid & 31;
        const int col = b ^ (4 * ((l >> 3) & 3));
        const float2* xp = reinterpret_cast<const float2*>(
            x + (size_t)(bg0 + b) * kI);
        #pragma unroll
        for (int i = 0; i < 4; ++i) {
            float2 v = __ldcg(xp + l + 32 * i);
            Hd[(KP_H + l + 32 * i) * HD_STRIDE + col] =
                *reinterpret_cast<unsigned long long*>(&v);
        }
    }
    __syncthreads();
    const unsigned base = Aux[0];

    // ---- per-thread geometry ------------------------------------------------
    const int w    = tid >> 5;
    const int lane = tid & 31;
    const int jq   = lane & 7;
    const int bp   = lane >> 3;
    const int rb   = w, rl = lane;

    const unsigned* flagp = g_rnn_flag + (g * NC + w);
    unsigned* myflag = g_rnn_flag + blockIdx.x;

    // h readback geometry (warp w <- producer CTA (g,w), j in [32w,32w+32))
    const int p    = lane & 15;
    const int bh   = (lane >> 4) * 8;
    const int pge8 = (p >> 3) & 1;
    const int hswz = 4 * ((2 * w + pge8) & 3);

    // warp-private x staging geometry: rows KP_H+8w+r, r = lane&7
    const int xr_row = lane & 7;
    const int xq     = lane >> 3;
    const int xswz   = 4 * (w & 3);

    const unsigned long long* wx  = Ws + (size_t)(KP_H + XW * w) * WS_STRIDE + jq * 2;
    const unsigned long long* hx  = Hd + (size_t)(KP_H + XW * w) * HD_STRIDE
                                       + 4 * (bp ^ (w & 3));
    const unsigned long long* wh0 = Ws + (size_t)(HW * w) * WS_STRIDE + jq * 2;
    const unsigned long long* hh0 = Hd + (size_t)(HW * w) * HD_STRIDE
                                       + 4 * (bp ^ ((2 * w) & 3));
    const unsigned long long* wh1 = Ws + (size_t)(HW * w + 8) * WS_STRIDE + jq * 2;
    const unsigned long long* hh1 = Hd + (size_t)(HW * w + 8) * HD_STRIDE
                                       + 4 * (bp ^ ((2 * w + 1) & 3));

    unsigned long long acc[16];

    // ---- x-part for t=0 ------------------------------------------------------
    {
        #pragma unroll
        for (int i = 0; i < 16; ++i) acc[i] = 0ull;
        const unsigned long long* wp = wx;
        const unsigned long long* hp = hx;
        #pragma unroll
        for (int i = 0; i < XW; ++i) { STEP16(wp, hp); wp += WS_STRIDE; hp += HD_STRIDE; }
    }

    for (int t = 0; t < kT; ++t) {
        float* Psb = Ps + (t & 1) * PS_FLOATS;

        // ---- h-part ----------------------------------------------------------
        {
            const unsigned long long* wp = wh0;
            const unsigned long long* hp = hh0;
            #pragma unroll
            for (int i = 0; i < 8; ++i) { STEP16(wp, hp); wp += WS_STRIDE; hp += HD_STRIDE; }
            wp = wh1; hp = hh1;
            #pragma unroll
            for (int i = 0; i < 8; ++i) { STEP16(wp, hp); wp += WS_STRIDE; hp += HD_STRIDE; }
        }

        // ---- scatter partials (conflict-free) --------------------------------
        #pragma unroll
        for (int bb = 0; bb < 4; ++bb) {
            const int row = (w * BG + 4 * bp + bb) * PS_STRIDE;
            #pragma unroll
            for (int jj = 0; jj < 4; ++jj) {
                float2 f = *reinterpret_cast<float2*>(&acc[jj * 4 + bb]);
                Psb[row + jj * 8 + jq] = f.x + f.y;
            }
        }

        // ---- issue x[t+1] loads (warp-private rows) ---------------------------
        float2 xv[4];
        if (t + 1 < kT) {
            #pragma unroll
            for (int i = 0; i < 4; ++i) {
                const int b = 4 * xq + i;
                xv[i] = __ldcg(reinterpret_cast<const float2*>(
                    x + (size_t)(t + 1) * kB * kI + (size_t)(bg0 + b) * kI)
                    + (XW * w + xr_row));
            }
        }
        __syncthreads();                                   // S1: Ps ready

        // ---- reduce, tanh, store out[t] ----------------------------------------
        {
            const int cf = (rl & 3) * 8 + (rl >> 2);
            float pv[16];
            #pragma unroll
            for (int ws = 0; ws < NWARP; ++ws)
                pv[ws] = Psb[(ws * BG + rb) * PS_STRIDE + cf];
            #pragma unroll
            for (int s = 8; s >= 1; s >>= 1)
                #pragma unroll
                for (int i = 0; i < s; ++i) pv[i] += pv[i + s];
            float r = tanhf(pv[0]);
            size_t o = (size_t)t * kB * kH + (size_t)(bg0 + rb) * kH + jg0 + rl;
            out[o] = r;
            if (t == kT - 1 && write_tail)
                out[(size_t)kT * kB * kH + (size_t)(bg0 + rb) * kH + jg0 + rl] = r;
        }
        if (t + 1 == kT) break;

        // ---- de-blocked release: only warp 0 waits -----------------------------
        if (w == 0) {
            asm volatile("bar.sync 1, %0;" :: "r"(NTHR) : "memory");
            if (lane == 0) {
                asm volatile("fence.acq_rel.gpu;" ::: "memory");
                asm volatile("red.release.gpu.global.add.u32 [%0], %1;"
                             :: "l"(myflag), "r"(1u) : "memory");
            }
        } else {
            asm volatile("bar.arrive 1, %0;" :: "r"(NTHR) : "memory");
        }

        // ---- stage x[t+1] into OWN rows (warp-private, no barrier) --------------
        #pragma unroll
        for (int i = 0; i < 4; ++i) {
            const int b = 4 * xq + i;
            Hd[(size_t)(KP_H + XW * w + xr_row) * HD_STRIDE + (b ^ xswz)] =
                *reinterpret_cast<unsigned long long*>(&xv[i]);
        }

        // ---- early relaxed poll (latency hidden under x-part) -------------------
        unsigned early;
        asm volatile("ld.relaxed.gpu.global.u32 %0, [%1];"
                     : "=r"(early) : "l"(flagp) : "memory");

        // ---- x-part(t+1): overlaps release->visibility --------------------------
        {
            #pragma unroll
            for (int i = 0; i < 16; ++i) acc[i] = 0ull;
            const unsigned long long* wp = wx;
            const unsigned long long* hp = hx;
            #pragma unroll
            for (int i = 0; i < XW; ++i) { STEP16(wp, hp); wp += WS_STRIDE; hp += HD_STRIDE; }
        }

        // ---- wait producer flag, read h slice, stage (warp-private) -------------
        {
            const unsigned target = base + (unsigned)(t + 1);
            if ((int)(early - target) >= 0) {
                asm volatile("fence.acq_rel.gpu;" ::: "memory");  // upgrade relaxed obs
            } else {
                unsigned cur;
                do {
                    asm volatile("ld.acquire.gpu.global.u32 %0, [%1];"
                                 : "=r"(cur) : "l"(flagp) : "memory");
                } while ((int)(cur - target) < 0);
            }

            const float* hb = out + (size_t)t * kB * kH + (size_t)bg0 * kH
                                  + 32 * w + 2 * p;
            float2 hv[8];
            #pragma unroll
            for (int i = 0; i < 8; ++i) {
                const int brd = ((((2 * i) & 6) | (i >> 2)) ^ pge8);
                hv[i] = __ldcg(reinterpret_cast<const float2*>(
                    hb + (size_t)(bh + brd) * kH));
            }
            #pragma unroll
            for (int i = 0; i < 8; ++i) {
                const int brd = ((((2 * i) & 6) | (i >> 2)) ^ pge8);
                Hd[(16 * w + p) * HD_STRIDE + ((bh + brd) ^ hswz)] =
                    *reinterpret_cast<unsigned long long*>(&hv[i]);
            }
            __syncwarp();
        }
    }
}

extern "C" void kernel_launch(void* const* d_in, const int* in_sizes, int n_in,
                              void* d_out, int out_size) {
    const float* x  = (const float*)d_in[0];   // [T,B,I]
    const float* Wi = (const float*)d_in[1];   // [H,I]
    const float* Wh = (const float*)d_in[2];   // [H,H]
    float* out = (float*)d_out;

    const long long main_elems = (long long)kT * kB * kH;
    int write_tail = ((long long)out_size >= main_elems + (long long)kB * kH) ? 1 : 0;

    cudaFuncSetAttribute(rnn_deblk_kernel,
                         cudaFuncAttributeMaxDynamicSharedMemorySize,
                         (int)SMEM_BYTES);
    rnn_deblk_kernel<<<NG * NC, NTHR, SMEM_BYTES>>>(x, Wi, Wh, out, write_tail);
}